// round 3
// baseline (speedup 1.0000x reference)
#include <cuda_runtime.h>
#include <math.h>

#define NS      4194304
#define NFFT    512
#define HOP     128
#define NT      32769          // frames = 1 + NS/HOP
#define NF      257            // rfft bins
#define NSC     32768          // scan length (= NT-1 = 2^15)
#define OSTRIDE 771            // 3*NF

#define PI_F   0x1.921fb6p+1f  // float32(np.pi)
#define TPI_F  0x1.921fb6p+2f  // float32(2*np.pi)

// ---------------- device scratch (statics: no runtime allocation) ----------
__device__ float  g_phase_tf[NT * NF];   // phase, [t][f]
__device__ float  g_phase[NF * NT];      // phase, [f][t]
__device__ float  g_pc[NF * NSC];        // ph_correct, [f][i]
__device__ float  g_dem[NF * NT];        // demod phase, [f][t]
__device__ double g_psum[1024];
__device__ double g_psq[1024];
__device__ float  g_c;                   // mean/std scalar
__device__ float  g_win[NFFT];
__device__ float2 g_tw[256];             // exp(-i*pi*j/256)

// ---------------- init: window + twiddles ----------------------------------
__global__ void k_init() {
    int t = threadIdx.x;                 // 512 threads
    if (t < NFFT) {
        // ref: hann = 0.5*(1 - cos(fl(2pi_f32 * k) / 512)) ; /512 exact
        float a = __fmul_rn(TPI_F, (float)t) * (1.0f / 512.0f);
        g_win[t] = (float)(0.5 * (1.0 - cos((double)a)));
    }
    if (t < 256) {
        double s, c;
        sincospi(-(double)t / 256.0, &s, &c);
        g_tw[t] = make_float2((float)c, (float)s);
    }
}

// ---------------- deterministic mean / sumsq reduction ----------------------
__global__ void k_reduce(const float* __restrict__ audio) {
    __shared__ double ss[256], sq[256];
    int tid = threadIdx.x, bid = blockIdx.x;
    double s = 0.0, q = 0.0;
    for (int i = bid * 256 + tid; i < NS; i += 1024 * 256) {
        double v = (double)audio[i];
        s += v; q += v * v;
    }
    ss[tid] = s; sq[tid] = q;
    __syncthreads();
    for (int w = 128; w > 0; w >>= 1) {
        if (tid < w) { ss[tid] += ss[tid + w]; sq[tid] += sq[tid + w]; }
        __syncthreads();
    }
    if (tid == 0) { g_psum[bid] = ss[0]; g_psq[bid] = sq[0]; }
}

__global__ void k_final() {
    double s = 0.0, q = 0.0;
    for (int i = 0; i < 1024; i++) { s += g_psum[i]; q += g_psq[i]; }
    double mean = s / (double)NS;
    double var  = (q - s * s / (double)NS) / (double)(NS - 1);
    float mf = (float)mean;
    float sf = (float)sqrt(var);
    g_c = mf / sf;                       // f32 divide, like the reference
}

// ---------------- STFT: 2 real frames per 512-pt complex FFT ---------------
__device__ __forceinline__ float ld_reflect(const float* __restrict__ a, int pos) {
    if (pos < 0) pos = -pos;
    else if (pos >= NS) pos = 2 * NS - 2 - pos;
    return a[pos];
}

__global__ void __launch_bounds__(256) k_stft(const float* __restrict__ audio,
                                              float* __restrict__ out) {
    __shared__ float2 sx[NFFT];
    __shared__ float2 stw[256];

    int tid = threadIdx.x;
    int p   = blockIdx.x;
    int t0  = 2 * p;
    int t1  = t0 + 1;
    bool has1 = (t1 < NT);

    stw[tid] = g_tw[tid];
    float c = g_c;

    // z[n] = fl((xa-c)*w) + i*fl((xb-c)*w), stored bit-reversed for DIT
#pragma unroll
    for (int rep = 0; rep < 2; rep++) {
        int n = tid + rep * 256;
        float w = g_win[n];
        int base = t0 * HOP + n - 256;
        float va = (ld_reflect(audio, base) - c) * w;
        float vb = has1 ? (ld_reflect(audio, base + HOP) - c) * w : 0.0f;
        int rv = __brev((unsigned)n) >> 23;
        sx[rv] = make_float2(va, vb);
    }
    __syncthreads();

    // radix-2 DIT, 9 stages, correctly-rounded twiddles
#pragma unroll
    for (int s = 1; s <= 9; s++) {
        int mh  = 1 << (s - 1);
        int grp = tid >> (s - 1);
        int pos = tid & (mh - 1);
        int i0  = (grp << s) + pos;
        int i1  = i0 + mh;
        float2 w = stw[pos << (9 - s)];
        float2 a = sx[i0];
        float2 b = sx[i1];
        float tr = b.x * w.x - b.y * w.y;
        float ti = b.x * w.y + b.y * w.x;
        sx[i0] = make_float2(a.x + tr, a.y + ti);
        sx[i1] = make_float2(a.x - tr, a.y - ti);
        __syncthreads();
    }

    for (int kk = tid; kk < NF; kk += 256) {
        float2 Z1 = sx[kk];
        float2 Z2 = sx[(NFFT - kk) & (NFFT - 1)];
        {   // frame t0: X = (Z1 + conj(Z2))/2
            float re = 0.5f * (Z1.x + Z2.x);
            float im = 0.5f * (Z1.y - Z2.y);
            float mag = sqrtf(fmaf(re, re, im * im));
            out[t0 * OSTRIDE + kk] = logf(mag + 1e-9f);
            g_phase_tf[t0 * NF + kk] = atan2f(im, re);
        }
        if (has1) { // frame t1: X = (Z1 - conj(Z2))/(2i)
            float re = 0.5f * (Z1.y + Z2.y);
            float im = 0.5f * (Z2.x - Z1.x);
            float mag = sqrtf(fmaf(re, re, im * im));
            out[t1 * OSTRIDE + kk] = logf(mag + 1e-9f);
            g_phase_tf[t1 * NF + kk] = atan2f(im, re);
        }
    }
}

// ---------------- transpose phase [t][f] -> [f][t] --------------------------
__global__ void k_tr1() {
    __shared__ float tile[32][33];
    int t = blockIdx.x * 32 + threadIdx.x;
    int f = blockIdx.y * 32 + threadIdx.y;
    if (t < NT && f < NF) tile[threadIdx.y][threadIdx.x] = g_phase_tf[t * NF + f];
    __syncthreads();
    int f2 = blockIdx.y * 32 + threadIdx.x;
    int t2 = blockIdx.x * 32 + threadIdx.y;
    if (f2 < NF && t2 < NT) g_phase[f2 * NT + t2] = tile[threadIdx.x][threadIdx.y];
}

// ---------------- ph_correct, exact jnp op sequence -------------------------
__global__ void __launch_bounds__(256) k_pc() {
    int f = blockIdx.y;
    int i = blockIdx.x * 256 + threadIdx.x;      // 0..32767
    const float* ph = g_phase + f * NT;
    float p0 = ph[i];
    float p1 = ph[i + 1];
    float dd = p1 - p0;
    float t  = dd + PI_F;
    float r  = fmodf(t, TPI_F);                  // exact trunc remainder
    if (r != 0.0f && r < 0.0f) r += TPI_F;       // jnp.mod sign fixup
    float ddmod = r - PI_F;
    if (ddmod == -PI_F && dd > 0.0f) ddmod = PI_F;
    float pc = (fabsf(dd) < PI_F) ? 0.0f : (ddmod - dd);
    g_pc[f * NSC + i] = pc;
}

// ---------------- bit-exact jax associative_scan tree -----------------------
__global__ void __launch_bounds__(1024) k_scan() {
    extern __shared__ float lv[];                // 32767 floats: levels 1..15
    int f   = blockIdx.x;
    int tid = threadIdx.x;
    const float* pc = g_pc    + f * NSC;
    const float* ph = g_phase + f * NT;
    float* dem      = g_dem   + f * NT;

    // upsweep: level1..level15 pair sums
    for (int i = tid; i < 16384; i += 1024)
        lv[i] = pc[2 * i] + pc[2 * i + 1];
    __syncthreads();
    int off = 0, n = 16384;
    while (n > 1) {
        int half = n >> 1;
        for (int i = tid; i < half; i += 1024)
            lv[off + n + i] = lv[off + 2 * i] + lv[off + 2 * i + 1];
        __syncthreads();
        off += n; n = half;
    }
    // downsweep (in place): S_k[0]=L_k[0]; S_k[2i+1]=S_{k+1}[i]; S_k[2i+2]=S_{k+1}[i]+L_k[2i+2]
    int off_hi = off;                            // level 15 at 32766
    for (int k = 14; k >= 1; k--) {
        int nk    = 32768 >> k;
        int off_k = off_hi - nk;
        int half  = nk >> 1;
        for (int i = tid; i < half; i += 1024) {
            float s = lv[off_hi + i];
            lv[off_k + 2 * i + 1] = s;
            if (i < half - 1) lv[off_k + 2 * i + 2] += s;
        }
        __syncthreads();
        off_hi = off_k;
    }
    // lv[0..16383] = S_1 ; demod[j] = ph[j] + S_0[j-1], S_0 from S_1 + pc
    if (tid == 0) {
        dem[0] = ph[0];
        dem[1] = ph[1] + pc[0];
    }
    for (int i = tid; i < 16384; i += 1024) {
        float s1 = lv[i];
        dem[2 * i + 2] = ph[2 * i + 2] + s1;                       // S_0[2i+1]=S_1[i]
        if (i < 16383)
            dem[2 * i + 3] = ph[2 * i + 3] + (s1 + pc[2 * i + 2]); // S_0[2i+2]
    }
}

// ---------------- emit sin/cos, tiled transpose [f][t] -> [t][3][f] --------
__global__ void k_emit(float* __restrict__ out) {
    __shared__ float tile[32][33];
    int t = blockIdx.x * 32 + threadIdx.x;
    int f = blockIdx.y * 32 + threadIdx.y;
    if (t < NT && f < NF) tile[threadIdx.y][threadIdx.x] = g_dem[f * NT + t];
    __syncthreads();
    int f2 = blockIdx.y * 32 + threadIdx.x;
    int t2 = blockIdx.x * 32 + threadIdx.y;
    if (f2 < NF && t2 < NT) {
        float s, c;
        sincosf(tile[threadIdx.x][threadIdx.y], &s, &c);
        out[t2 * OSTRIDE + 257 + f2] = s;
        out[t2 * OSTRIDE + 514 + f2] = c;
    }
}

// ---------------------------------------------------------------------------
extern "C" void kernel_launch(void* const* d_in, const int* in_sizes, int n_in,
                              void* d_out, int out_size) {
    (void)in_sizes; (void)n_in; (void)out_size;
    const float* audio = (const float*)d_in[0];
    float* out = (float*)d_out;

    // idempotent, stream-independent; no static guard (harness rule)
    cudaFuncSetAttribute(k_scan, cudaFuncAttributeMaxDynamicSharedMemorySize,
                         32767 * (int)sizeof(float));

    k_init<<<1, 512>>>();
    k_reduce<<<1024, 256>>>(audio);
    k_final<<<1, 1>>>();
    k_stft<<<(NT + 1) / 2, 256>>>(audio, out);
    {
        dim3 b(32, 32), g((NT + 31) / 32, (NF + 31) / 32);
        k_tr1<<<g, b>>>();
    }
    {
        dim3 g(NSC / 256, NF);
        k_pc<<<g, 256>>>();
    }
    k_scan<<<NF, 1024, 32767 * sizeof(float)>>>();
    {
        dim3 b(32, 32), g((NT + 31) / 32, (NF + 31) / 32);
        k_emit<<<g, b>>>(out);
    }
}

// round 4
// speedup vs baseline: 1.5949x; 1.5949x over previous
#include <cuda_runtime.h>
#include <math.h>

#define NS      4194304
#define NFFT    512
#define HOP     128
#define NT      32769          // frames = 1 + NS/HOP
#define NF      257            // rfft bins
#define NSC     32768          // scan length (= NT-1 = 2^15)
#define OSTRIDE 771            // 3*NF

#define PI_F   0x1.921fb6p+1f  // float32(np.pi)
#define TPI_F  0x1.921fb6p+2f  // float32(2*np.pi)

// ---------------- device scratch (statics: no runtime allocation) ----------
__device__ float  g_phase_tf[NT * NF];   // phase, [t][f]
__device__ float  g_phase[NF * NT];      // phase, [f][t]
__device__ float  g_dem[NF * NT];        // demod phase, [f][t]
__device__ double g_psum[1024];
__device__ double g_psq[1024];
__device__ float  g_c;                   // mean/std scalar
__device__ float  g_win[NFFT];
__device__ float2 g_tw[256];             // W_512^j = exp(-i*pi*j/256)

// ---------------- init: window + twiddles ----------------------------------
__global__ void k_init() {
    int t = threadIdx.x;                 // 512 threads
    if (t < NFFT) {
        float a = __fmul_rn(TPI_F, (float)t) * (1.0f / 512.0f);
        g_win[t] = (float)(0.5 * (1.0 - cos((double)a)));
    }
    if (t < 256) {
        double s, c;
        sincospi(-(double)t / 256.0, &s, &c);
        g_tw[t] = make_float2((float)c, (float)s);
    }
}

// ---------------- deterministic mean / sumsq reduction ----------------------
__global__ void k_reduce(const float* __restrict__ audio) {
    __shared__ double ss[256], sq[256];
    int tid = threadIdx.x, bid = blockIdx.x;
    double s = 0.0, q = 0.0;
    for (int i = bid * 256 + tid; i < NS; i += 1024 * 256) {
        double v = (double)audio[i];
        s += v; q += v * v;
    }
    ss[tid] = s; sq[tid] = q;
    __syncthreads();
    for (int w = 128; w > 0; w >>= 1) {
        if (tid < w) { ss[tid] += ss[tid + w]; sq[tid] += sq[tid + w]; }
        __syncthreads();
    }
    if (tid == 0) { g_psum[bid] = ss[0]; g_psq[bid] = sq[0]; }
}

__global__ void k_final() {
    __shared__ double ss[1024], sq[1024];
    int tid = threadIdx.x;
    ss[tid] = g_psum[tid]; sq[tid] = g_psq[tid];
    __syncthreads();
    for (int w = 512; w > 0; w >>= 1) {
        if (tid < w) { ss[tid] += ss[tid + w]; sq[tid] += sq[tid + w]; }
        __syncthreads();
    }
    if (tid == 0) {
        double s = ss[0], q = sq[0];
        double mean = s / (double)NS;
        double var  = (q - s * s / (double)NS) / (double)(NS - 1);
        g_c = (float)mean / (float)sqrt(var);   // f32 divide, like the reference
    }
}

// ---------------- STFT: register-blocked 512-pt FFT -------------------------
// 64 threads per FFT (8 complex regs each), 4 FFTs (8 real frames) per block.
// DIF radix-2: stages 1-3 in regs, transpose, 4-6 in regs, transpose, 7-9 in
// regs, final store + rfft extraction. 2 real frames packed per complex FFT.
__device__ __forceinline__ float ld_reflect(const float* __restrict__ a, int pos) {
    if (pos < 0) pos = -pos;
    else if (pos >= NS) pos = 2 * NS - 2 - pos;
    return a[pos];
}

#define CBFLY(A, B, W) do {                          \
    float _tr = (A).x - (B).x, _ti = (A).y - (B).y;  \
    (A).x += (B).x; (A).y += (B).y;                  \
    (B).x = _tr * (W).x - _ti * (W).y;               \
    (B).y = _tr * (W).y + _ti * (W).x;               \
} while (0)

__global__ void __launch_bounds__(256) k_stft(const float* __restrict__ audio,
                                              float* __restrict__ out) {
    __shared__ float2 stw[256];
    __shared__ float2 sbuf[4 * 576];     // per-slot padded FFT workspace

    int tid  = threadIdx.x;
    stw[tid] = g_tw[tid];
    int slot = tid >> 6;
    int l    = tid & 63;
    float2* S = sbuf + slot * 576;

    int t0 = blockIdx.x * 8 + slot * 2;
    int t1 = t0 + 1;
    bool v0 = t0 < NT, v1 = t1 < NT;
    float c = g_c;

    float2 z[8];
#pragma unroll
    for (int j = 0; j < 8; j++) {
        int n = 64 * j + l;
        float w = g_win[n];
        int base = t0 * HOP + n - 256;
        float va = (ld_reflect(audio, base) - c) * w;
        float vb = (ld_reflect(audio, base + HOP) - c) * w;
        z[j] = make_float2(va, vb);
    }
    __syncthreads();          // stw visible

    // stages 1-3 (half-spans 256,128,64), thread holds x[64j + l]
#pragma unroll
    for (int j = 0; j < 4; j++) { float2 w = stw[64 * j + l]; CBFLY(z[j], z[j + 4], w); }
    {
        float2 wa = stw[2 * l], wb = stw[2 * (64 + l)];
        CBFLY(z[0], z[2], wa); CBFLY(z[1], z[3], wb);
        CBFLY(z[4], z[6], wa); CBFLY(z[5], z[7], wb);
    }
    {
        float2 w = stw[4 * l];
        CBFLY(z[0], z[1], w); CBFLY(z[2], z[3], w);
        CBFLY(z[4], z[5], w); CBFLY(z[6], z[7], w);
    }

    // transpose 1: pitch-65 rows to avoid bank conflicts
#pragma unroll
    for (int j = 0; j < 8; j++) S[j * 65 + l] = z[j];
    __syncthreads();
    int c8 = l >> 3, s8 = l & 7;
#pragma unroll
    for (int u = 0; u < 8; u++) z[u] = S[c8 * 65 + 8 * u + s8];

    // stages 4-6 (32,16,8): index i = c8*64 + 8u + s8
#pragma unroll
    for (int u = 0; u < 4; u++) { float2 w = stw[8 * (8 * u + s8)]; CBFLY(z[u], z[u + 4], w); }
    {
        float2 wa = stw[16 * s8], wb = stw[16 * (8 + s8)];
        CBFLY(z[0], z[2], wa); CBFLY(z[1], z[3], wb);
        CBFLY(z[4], z[6], wa); CBFLY(z[5], z[7], wb);
    }
    {
        float2 w = stw[32 * s8];
        CBFLY(z[0], z[1], w); CBFLY(z[2], z[3], w);
        CBFLY(z[4], z[5], w); CBFLY(z[6], z[7], w);
    }

    // transpose 2: group-major, pitch 9
    __syncthreads();
#pragma unroll
    for (int u = 0; u < 8; u++) S[(c8 * 8 + u) * 9 + s8] = z[u];
    __syncthreads();
#pragma unroll
    for (int v = 0; v < 8; v++) z[v] = S[l * 9 + v];

    // stages 7-9 (4,2,1): index i = 8l + v
#pragma unroll
    for (int v = 0; v < 4; v++) { float2 w = stw[64 * v]; CBFLY(z[v], z[v + 4], w); }
    {   // span 2: tw = 1 (v even base) or -i
        float2 t;
        t.x = z[0].x - z[2].x; t.y = z[0].y - z[2].y; z[0].x += z[2].x; z[0].y += z[2].y; z[2] = t;
        t.x = z[1].x - z[3].x; t.y = z[1].y - z[3].y; z[1].x += z[3].x; z[1].y += z[3].y;
        z[3] = make_float2(t.y, -t.x);
        t.x = z[4].x - z[6].x; t.y = z[4].y - z[6].y; z[4].x += z[6].x; z[4].y += z[6].y; z[6] = t;
        t.x = z[5].x - z[7].x; t.y = z[5].y - z[7].y; z[5].x += z[7].x; z[5].y += z[7].y;
        z[7] = make_float2(t.y, -t.x);
    }
    {   // span 1: tw = 1
        float2 t;
#pragma unroll
        for (int v = 0; v < 8; v += 2) {
            t.x = z[v].x - z[v + 1].x; t.y = z[v].y - z[v + 1].y;
            z[v].x += z[v + 1].x; z[v].y += z[v + 1].y; z[v + 1] = t;
        }
    }

    // final store (swizzled), then rfft extraction via bit-reversed index
    __syncthreads();
#pragma unroll
    for (int v = 0; v < 8; v++) {
        int idx = 8 * l + v;
        S[idx ^ ((idx >> 3) & 7)] = z[v];
    }
    __syncthreads();

    for (int kk = l; kk < NF; kk += 64) {
        int i1 = __brev((unsigned)kk) >> 23;
        int i2 = __brev((unsigned)((NFFT - kk) & (NFFT - 1))) >> 23;
        float2 Z1 = S[i1 ^ ((i1 >> 3) & 7)];
        float2 Z2 = S[i2 ^ ((i2 >> 3) & 7)];
        if (v0) {   // frame t0: X = (Z1 + conj(Z2))/2
            float re = 0.5f * (Z1.x + Z2.x);
            float im = 0.5f * (Z1.y - Z2.y);
            float mag = sqrtf(fmaf(re, re, im * im));
            out[t0 * OSTRIDE + kk] = logf(mag + 1e-9f);
            g_phase_tf[t0 * NF + kk] = atan2f(im, re);
        }
        if (v1) {   // frame t1: X = (Z1 - conj(Z2))/(2i)
            float re = 0.5f * (Z1.y + Z2.y);
            float im = 0.5f * (Z2.x - Z1.x);
            float mag = sqrtf(fmaf(re, re, im * im));
            out[t1 * OSTRIDE + kk] = logf(mag + 1e-9f);
            g_phase_tf[t1 * NF + kk] = atan2f(im, re);
        }
    }
}

// ---------------- transpose phase [t][f] -> [f][t] --------------------------
__global__ void k_tr1() {
    __shared__ float tile[32][33];
    int t = blockIdx.x * 32 + threadIdx.x;
    int f = blockIdx.y * 32 + threadIdx.y;
    if (t < NT && f < NF) tile[threadIdx.y][threadIdx.x] = g_phase_tf[t * NF + f];
    __syncthreads();
    int f2 = blockIdx.y * 32 + threadIdx.x;
    int t2 = blockIdx.x * 32 + threadIdx.y;
    if (f2 < NF && t2 < NT) g_phase[f2 * NT + t2] = tile[threadIdx.x][threadIdx.y];
}

// ---------------- ph_correct, exact jnp op sequence (inlined) ---------------
__device__ __forceinline__ float pcf(float p0, float p1) {
    float dd = p1 - p0;
    float t  = dd + PI_F;
    float r  = fmodf(t, TPI_F);                  // exact trunc remainder
    if (r != 0.0f && r < 0.0f) r += TPI_F;       // jnp.mod sign fixup
    float ddmod = r - PI_F;
    if (ddmod == -PI_F && dd > 0.0f) ddmod = PI_F;
    return (fabsf(dd) < PI_F) ? 0.0f : (ddmod - dd);
}

// ---------------- bit-exact jax associative_scan tree (pc fused) ------------
__global__ void __launch_bounds__(1024) k_scan() {
    extern __shared__ float lv[];                // 32767 floats: levels 1..15
    int f   = blockIdx.x;
    int tid = threadIdx.x;
    const float* ph = g_phase + f * NT;
    float* dem      = g_dem   + f * NT;

    // upsweep level 1 straight from phase (pc recomputed inline)
    for (int i = tid; i < 16384; i += 1024) {
        float p0 = ph[2 * i], p1 = ph[2 * i + 1], p2 = ph[2 * i + 2];
        lv[i] = pcf(p0, p1) + pcf(p1, p2);
    }
    __syncthreads();
    int off = 0, n = 16384;
    while (n > 1) {
        int half = n >> 1;
        for (int i = tid; i < half; i += 1024)
            lv[off + n + i] = lv[off + 2 * i] + lv[off + 2 * i + 1];
        __syncthreads();
        off += n; n = half;
    }
    // downsweep (in place): S_k[2i+1]=S_{k+1}[i]; S_k[2i+2]=S_{k+1}[i]+L_k[2i+2]
    int off_hi = off;                            // level 15 at 32766
    for (int k = 14; k >= 1; k--) {
        int nk    = 32768 >> k;
        int off_k = off_hi - nk;
        int half  = nk >> 1;
        for (int i = tid; i < half; i += 1024) {
            float s = lv[off_hi + i];
            lv[off_k + 2 * i + 1] = s;
            if (i < half - 1) lv[off_k + 2 * i + 2] += s;
        }
        __syncthreads();
        off_hi = off_k;
    }
    // lv[0..16383] = S_1 ; demod[j] = ph[j] + S_0[j-1]
    if (tid == 0) {
        float p0 = ph[0], p1 = ph[1];
        dem[0] = p0;
        dem[1] = p1 + pcf(p0, p1);
    }
    for (int i = tid; i < 16384; i += 1024) {
        float s1 = lv[i];
        float pa = ph[2 * i + 2];
        dem[2 * i + 2] = pa + s1;                               // S_0[2i+1]=S_1[i]
        if (i < 16383) {
            float pb = ph[2 * i + 3];
            dem[2 * i + 3] = pb + (s1 + pcf(pa, pb));           // S_0[2i+2]
        }
    }
}

// ---------------- emit sin/cos, tiled transpose [f][t] -> [t][3][f] --------
__global__ void k_emit(float* __restrict__ out) {
    __shared__ float tile[32][33];
    int t = blockIdx.x * 32 + threadIdx.x;
    int f = blockIdx.y * 32 + threadIdx.y;
    if (t < NT && f < NF) tile[threadIdx.y][threadIdx.x] = g_dem[f * NT + t];
    __syncthreads();
    int f2 = blockIdx.y * 32 + threadIdx.x;
    int t2 = blockIdx.x * 32 + threadIdx.y;
    if (f2 < NF && t2 < NT) {
        float s, c;
        sincosf(tile[threadIdx.x][threadIdx.y], &s, &c);
        out[t2 * OSTRIDE + 257 + f2] = s;
        out[t2 * OSTRIDE + 514 + f2] = c;
    }
}

// ---------------------------------------------------------------------------
extern "C" void kernel_launch(void* const* d_in, const int* in_sizes, int n_in,
                              void* d_out, int out_size) {
    (void)in_sizes; (void)n_in; (void)out_size;
    const float* audio = (const float*)d_in[0];
    float* out = (float*)d_out;

    cudaFuncSetAttribute(k_scan, cudaFuncAttributeMaxDynamicSharedMemorySize,
                         32767 * (int)sizeof(float));

    k_init<<<1, 512>>>();
    k_reduce<<<1024, 256>>>(audio);
    k_final<<<1, 1024>>>();
    k_stft<<<(NT + 7) / 8, 256>>>(audio, out);
    {
        dim3 b(32, 32), g((NT + 31) / 32, (NF + 31) / 32);
        k_tr1<<<g, b>>>();
    }
    k_scan<<<NF, 1024, 32767 * sizeof(float)>>>();
    {
        dim3 b(32, 32), g((NT + 31) / 32, (NF + 31) / 32);
        k_emit<<<g, b>>>(out);
    }
}